// round 6
// baseline (speedup 1.0000x reference)
#include <cuda_runtime.h>
#include <cuda_bf16.h>
#include <math.h>
#include <stdint.h>

// ---------------------------------------------------------------------------
// Problem constants
// ---------------------------------------------------------------------------
#define BATCH      8
#define T_FRAMES   2048
#define M_TOTAL    (BATCH * T_FRAMES)   // 16384 frames
#define K_DIM      512
#define N_DIM      1026                 // N_FFT + 2
#define N_PAD      1152                 // 9 * 128
#define NBINS      513                  // N_FFT/2 + 1
#define NFFT       1024
#define HOP        256
#define PAD        384                  // (1024-256)/2
#define OUT_FULL   ((T_FRAMES - 1) * HOP + NFFT)  // 525312
#define OUT_LEN    (OUT_FULL - 2 * PAD)           // 524544

// ---------------------------------------------------------------------------
// Scratch (device globals: no runtime allocation allowed)
// ---------------------------------------------------------------------------
__device__ float g_h[(size_t)M_TOTAL * N_DIM];        // linear head output (~67 MB)
__device__ float g_frames[(size_t)M_TOTAL * NFFT];    // windowed iFFT frames (~67 MB)
__device__ __nv_bfloat16 g_xhi[(size_t)M_TOTAL * K_DIM];
__device__ __nv_bfloat16 g_xlo[(size_t)M_TOTAL * K_DIM];
__device__ __nv_bfloat16 g_wthi[(size_t)N_PAD * K_DIM];
__device__ __nv_bfloat16 g_wtlo[(size_t)N_PAD * K_DIM];
// precomputed tables
__device__ float2 g_tw[256];        // e^{+2*pi*i*j/512},  j<256  (FFT twiddles)
__device__ float2 g_pretw[512];     // e^{+2*pi*i*k/1024}, k<512  (packing twiddles)
__device__ float  g_win[NFFT];      // hann window
__device__ float  g_env_inv[OUT_FULL];  // 1 / sum win^2

// ---------------------------------------------------------------------------
// baseline-arch PTX helpers (supported on compute_103 WITHOUT 'a')
// ---------------------------------------------------------------------------
__device__ __forceinline__ uint32_t smem_u32(const void* p) {
    return (uint32_t)__cvta_generic_to_shared(p);
}

__device__ __forceinline__ void cp_async16(uint32_t saddr, const void* gptr) {
    asm volatile("cp.async.cg.shared.global [%0], [%1], 16;"
                 :: "r"(saddr), "l"(gptr));
}
#define CP_COMMIT() asm volatile("cp.async.commit_group;" ::: "memory")
#define CP_WAIT0()  asm volatile("cp.async.wait_group 0;" ::: "memory")

#define LDSM_X4(r0, r1, r2, r3, addr) \
    asm volatile("ldmatrix.sync.aligned.m8n8.x4.shared.b16 {%0,%1,%2,%3}, [%4];" \
                 : "=r"(r0), "=r"(r1), "=r"(r2), "=r"(r3) : "r"(addr))

#define MMA16816(c, a0, a1, a2, a3, b0, b1) \
    asm volatile("mma.sync.aligned.m16n8k16.row.col.f32.bf16.bf16.f32 " \
                 "{%0,%1,%2,%3}, {%4,%5,%6,%7}, {%8,%9}, {%0,%1,%2,%3};" \
                 : "+f"((c)[0]), "+f"((c)[1]), "+f"((c)[2]), "+f"((c)[3]) \
                 : "r"(a0), "r"(a1), "r"(a2), "r"(a3), "r"(b0), "r"(b1))

// ---------------------------------------------------------------------------
// Prep: split x (fp32) into bf16 hi/lo
// ---------------------------------------------------------------------------
__global__ void __launch_bounds__(256)
split_x_kernel(const float* __restrict__ x)
{
    size_t i = ((size_t)blockIdx.x * 256 + threadIdx.x) * 8;
    float4 a = *(const float4*)(x + i);
    float4 b = *(const float4*)(x + i + 4);
    float v[8] = {a.x, a.y, a.z, a.w, b.x, b.y, b.z, b.w};
    union { __nv_bfloat16 h[8]; uint4 u; } H, L;
#pragma unroll
    for (int j = 0; j < 8; j++) {
        __nv_bfloat16 hi = __float2bfloat16(v[j]);
        H.h[j] = hi;
        L.h[j] = __float2bfloat16(v[j] - __bfloat162float(hi));
    }
    *(uint4*)&g_xhi[i] = H.u;
    *(uint4*)&g_xlo[i] = L.u;
}

// ---------------------------------------------------------------------------
// Prep: W [K, 1026] -> Wt hi/lo [1152, 512] bf16 (transposed, padded)
// ---------------------------------------------------------------------------
__global__ void __launch_bounds__(256)
prep_w_kernel(const float* __restrict__ W)
{
    int idx = blockIdx.x * 256 + threadIdx.x;
    if (idx >= N_PAD * K_DIM) return;
    int n = idx >> 9;
    int k = idx & 511;
    float v = (n < N_DIM) ? W[(size_t)k * N_DIM + n] : 0.0f;
    __nv_bfloat16 hi = __float2bfloat16(v);
    g_wthi[idx] = hi;
    g_wtlo[idx] = __float2bfloat16(v - __bfloat162float(hi));
}

// ---------------------------------------------------------------------------
// Prep: trig tables (twiddles, packing twiddles, hann window)
// ---------------------------------------------------------------------------
__global__ void __launch_bounds__(256)
tables_kernel()
{
    int i = blockIdx.x * 256 + threadIdx.x;     // 0..1023
    float s, c;
    if (i < 256) {                               // e^{2*pi*i*j/512}
        sincospif((float)i * (1.0f / 256.0f), &s, &c);
        g_tw[i] = make_float2(c, s);
    }
    if (i < 512) {                               // e^{2*pi*i*k/1024}
        sincospif((float)i * (1.0f / 512.0f), &s, &c);
        g_pretw[i] = make_float2(c, s);
    }
    if (i < NFFT) {
        g_win[i] = 0.5f * (1.0f - cospif((float)i * (1.0f / 512.0f)));
    }
}

// ---------------------------------------------------------------------------
// Prep: envelope reciprocal (batch-independent)
// ---------------------------------------------------------------------------
__global__ void __launch_bounds__(256)
env_kernel()
{
    int m = blockIdx.x * 256 + threadIdx.x;
    if (m >= OUT_FULL) return;
    int t_hi = m >> 8;
    if (t_hi > T_FRAMES - 1) t_hi = T_FRAMES - 1;
    int t_lo = (m >= (NFFT - HOP)) ? ((m - (NFFT - HOP)) >> 8) : 0;
    float env = 0.0f;
    for (int t = t_lo; t <= t_hi; t++) {
        int n = m - (t << 8);
        float win = 0.5f * (1.0f - cospif((float)n * (1.0f / 512.0f)));
        env += win * win;
    }
    g_env_inv[m] = (env > 0.0f) ? (1.0f / env) : 0.0f;
}

// ---------------------------------------------------------------------------
// Kernel 1: HMMA GEMM  h = x @ W + b  via 3x-bf16 split on mma.sync.m16n8k16.
// ---------------------------------------------------------------------------
#define MAT_BYTES   16384
#define STAGE_BYTES 65536
#define GEMM_SMEM   (2 * STAGE_BYTES)     // 128 KB

__device__ __forceinline__ void load_stage(uint32_t sdst,
                                           const __nv_bfloat16* const* srcs,
                                           int k0, int tid)
{
#pragma unroll
    for (int m = 0; m < 4; m++) {
        const __nv_bfloat16* __restrict__ src = srcs[m] + k0;
#pragma unroll
        for (int t = 0; t < 4; t++) {
            int idx = tid + (t << 8);
            int row = idx >> 3;
            int g   = idx & 7;
            uint32_t saddr = sdst + (m << 14) + (row << 7) + ((g ^ (row & 7)) << 4);
            cp_async16(saddr, src + (size_t)row * K_DIM + (g << 3));
        }
    }
}

__global__ void __launch_bounds__(256)
gemm_mma_kernel(const float* __restrict__ bias)
{
    extern __shared__ __align__(128) char smem[];
    const int tid  = threadIdx.x;
    const int lane = tid & 31;
    const int warp = tid >> 5;
    const int wm   = (warp >> 2) << 6;
    const int wn   = (warp & 3) << 5;
    const int bm   = blockIdx.y << 7;
    const int bn   = blockIdx.x << 7;
    const uint32_t sbase = smem_u32(smem);

    const __nv_bfloat16* srcs[4] = {
        g_xhi  + (size_t)bm * K_DIM,
        g_xlo  + (size_t)bm * K_DIM,
        g_wthi + (size_t)bn * K_DIM,
        g_wtlo + (size_t)bn * K_DIM
    };

    float acc[4][4][4];
#pragma unroll
    for (int i = 0; i < 4; i++)
#pragma unroll
        for (int j = 0; j < 4; j++)
#pragma unroll
            for (int r = 0; r < 4; r++) acc[i][j][r] = 0.0f;

    const int a_row  = wm + (lane & 15);
    const int a_gadd = (lane >> 4);
    const int b_row  = wn + (lane & 7) + ((lane >> 4) << 3);
    const int b_gadd = ((lane >> 3) & 1);

    load_stage(sbase, srcs, 0, tid);
    CP_COMMIT();

    for (int ck = 0; ck < K_DIM / 64; ck++) {
        CP_WAIT0();
        __syncthreads();
        if (ck + 1 < K_DIM / 64)
            load_stage(sbase + (((ck + 1) & 1) ? STAGE_BYTES : 0), srcs,
                       (ck + 1) << 6, tid);
        CP_COMMIT();

        const uint32_t stg = sbase + ((ck & 1) ? STAGE_BYTES : 0);

#pragma unroll
        for (int s16 = 0; s16 < 4; s16++) {
            const int g0 = (s16 << 1);
            uint32_t a[4][4], bh[2][4], bl[2][4];

#pragma unroll
            for (int i = 0; i < 4; i++) {
                int row = a_row + (i << 4);
                int g   = g0 + a_gadd;
                uint32_t addr = stg + (row << 7) + ((g ^ (row & 7)) << 4);
                LDSM_X4(a[i][0], a[i][1], a[i][2], a[i][3], addr);
            }
#pragma unroll
            for (int j2 = 0; j2 < 2; j2++) {
                int row = b_row + (j2 << 4);
                int g   = g0 + b_gadd;
                uint32_t boff = (row << 7) + ((g ^ (row & 7)) << 4);
                LDSM_X4(bh[j2][0], bh[j2][1], bh[j2][2], bh[j2][3],
                        stg + 2 * MAT_BYTES + boff);
                LDSM_X4(bl[j2][0], bl[j2][1], bl[j2][2], bl[j2][3],
                        stg + 3 * MAT_BYTES + boff);
            }
#pragma unroll
            for (int i = 0; i < 4; i++)
#pragma unroll
                for (int j = 0; j < 4; j++)
                    MMA16816(acc[i][j], a[i][0], a[i][1], a[i][2], a[i][3],
                             bh[j >> 1][(j & 1) << 1], bh[j >> 1][((j & 1) << 1) + 1]);
#pragma unroll
            for (int i = 0; i < 4; i++)
#pragma unroll
                for (int j = 0; j < 4; j++)
                    MMA16816(acc[i][j], a[i][0], a[i][1], a[i][2], a[i][3],
                             bl[j >> 1][(j & 1) << 1], bl[j >> 1][((j & 1) << 1) + 1]);
#pragma unroll
            for (int i = 0; i < 4; i++) {
                int row = a_row + (i << 4);
                int g   = g0 + a_gadd;
                uint32_t addr = stg + MAT_BYTES + (row << 7) + ((g ^ (row & 7)) << 4);
                LDSM_X4(a[i][0], a[i][1], a[i][2], a[i][3], addr);
            }
#pragma unroll
            for (int i = 0; i < 4; i++)
#pragma unroll
                for (int j = 0; j < 4; j++)
                    MMA16816(acc[i][j], a[i][0], a[i][1], a[i][2], a[i][3],
                             bh[j >> 1][(j & 1) << 1], bh[j >> 1][((j & 1) << 1) + 1]);
        }
    }

    const int r0 = bm + wm + (lane >> 2);
    const int c0 = bn + wn + ((lane & 3) << 1);
#pragma unroll
    for (int j = 0; j < 4; j++) {
        int col = c0 + (j << 3);
        if (col < N_DIM) {
            float bx = bias[col];
            float by = bias[col + 1];
#pragma unroll
            for (int i = 0; i < 4; i++) {
                int row = r0 + (i << 4);
                *(float2*)&g_h[(size_t)row * N_DIM + col] =
                    make_float2(acc[i][j][0] + bx, acc[i][j][1] + by);
                *(float2*)&g_h[(size_t)(row + 8) * N_DIM + col] =
                    make_float2(acc[i][j][2] + bx, acc[i][j][3] + by);
            }
        }
    }
}

// ---------------------------------------------------------------------------
// Kernel 2: per-frame spectrum -> HALF-SIZE (512-pt) complex inverse FFT via
// Hermitian packing -> window -> g_frames.
//   E = (X[k]+conj(X[512-k]))/2,  D = (X[k]-conj(X[512-k]))/2,
//   O = e^{+2pi i k/1024} * D,    Z = E + i*O,
//   z = ifft512(Z);  x[2n]=Re z[n], x[2n+1]=Im z[n]
// NOTE: irfft (pocketfft c2r) ignores Im(X[0]) and Im(X[512]) — zero them.
// ---------------------------------------------------------------------------
__global__ void __launch_bounds__(256)
ifft_kernel()
{
    __shared__ float2 spec[NBINS];       // 513 * 8B
    __shared__ float2 data[512];         // 4 KB
    __shared__ float2 tw[256];           // 2 KB

    const int f   = blockIdx.x;
    const int tid = threadIdx.x;
    const float* __restrict__ h = g_h + (size_t)f * N_DIM;

    // spectrum: S_k = min(exp(h_k),100) * (cos p_k + i sin p_k)
    for (int k = tid; k < NBINS; k += 256) {
        float mag = fminf(expf(h[k]), 100.0f);
        float s, c;
        sincosf(h[NBINS + k], &s, &c);
        // DC and Nyquist bins: irfft uses only the real part
        if (k == 0 || k == 512) s = 0.0f;
        spec[k] = make_float2(mag * c, mag * s);
    }
    tw[tid] = g_tw[tid];
    __syncthreads();

    // pack Z and store bit-reversed (9-bit)
#pragma unroll
    for (int l = 0; l < 2; l++) {
        int k = tid + (l << 8);
        float2 Xk = spec[k];
        float2 Xr = spec[512 - k];
        float Ex = 0.5f * (Xk.x + Xr.x);
        float Ey = 0.5f * (Xk.y - Xr.y);
        float Dx = 0.5f * (Xk.x - Xr.x);
        float Dy = 0.5f * (Xk.y + Xr.y);
        float2 w = g_pretw[k];
        float Ox = w.x * Dx - w.y * Dy;
        float Oy = w.x * Dy + w.y * Dx;
        int r = __brev((unsigned)k) >> 23;
        data[r] = make_float2(Ex - Oy, Ey + Ox);
    }
    __syncthreads();

    // 9 radix-2 DIT stages, one butterfly per thread per stage
#pragma unroll
    for (int s = 1; s <= 9; s++) {
        const int half = 1 << (s - 1);
        int j   = tid & (half - 1);
        int pos = ((tid >> (s - 1)) << s) + j;
        float2 w  = tw[j << (9 - s)];
        float2 lo = data[pos];
        float2 hi = data[pos + half];
        float2 t  = make_float2(w.x * hi.x - w.y * hi.y,
                                w.x * hi.y + w.y * hi.x);
        data[pos]        = make_float2(lo.x + t.x, lo.y + t.y);
        data[pos + half] = make_float2(lo.x - t.x, lo.y - t.y);
        __syncthreads();
    }

    // unpack: x[2n] = Re z[n], x[2n+1] = Im z[n]; scale 1/512; window
    const float inv = 1.0f / 512.0f;
    float* __restrict__ fr = g_frames + (size_t)f * NFFT;
#pragma unroll
    for (int l = 0; l < 2; l++) {
        int n = tid + (l << 8);
        float2 z  = data[n];
        float2 w2 = *(const float2*)&g_win[2 * n];
        *(float2*)&fr[2 * n] = make_float2(z.x * inv * w2.x, z.y * inv * w2.y);
    }
}

// ---------------------------------------------------------------------------
// Kernel 3: overlap-add (gather) * precomputed 1/env — no transcendentals
// ---------------------------------------------------------------------------
__global__ void __launch_bounds__(256)
ola_kernel(float* __restrict__ out)
{
    int i = blockIdx.x * blockDim.x + threadIdx.x;
    if (i >= BATCH * OUT_LEN) return;
    int b  = i / OUT_LEN;
    int mo = i - b * OUT_LEN;
    int m  = mo + PAD;

    int t_hi = m >> 8;
    if (t_hi > T_FRAMES - 1) t_hi = T_FRAMES - 1;
    int t_lo = (m >= (NFFT - HOP)) ? ((m - (NFFT - HOP)) >> 8) : 0;

    float acc = 0.0f;
    const float* __restrict__ base = g_frames + (size_t)b * T_FRAMES * NFFT;
#pragma unroll 4
    for (int t = t_lo; t <= t_hi; t++) {
        acc += base[(size_t)t * NFFT + (m - (t << 8))];
    }
    out[i] = acc * g_env_inv[m];
}

// ---------------------------------------------------------------------------
// Launch
// ---------------------------------------------------------------------------
extern "C" void kernel_launch(void* const* d_in, const int* in_sizes, int n_in,
                              void* d_out, int out_size)
{
    const float* x    = (const float*)d_in[0];   // [8, 2048, 512]
    const float* W    = (const float*)d_in[1];   // [512, 1026]
    const float* bias = (const float*)d_in[2];   // [1026]
    float* out = (float*)d_out;                  // [8, 524544]

    cudaFuncSetAttribute(gemm_mma_kernel,
                         cudaFuncAttributeMaxDynamicSharedMemorySize,
                         GEMM_SMEM);

    // 0) prep: bf16 splits + tables + envelope
    split_x_kernel<<<(M_TOTAL * K_DIM) / (256 * 8), 256>>>(x);
    prep_w_kernel<<<(N_PAD * K_DIM + 255) / 256, 256>>>(W);
    tables_kernel<<<4, 256>>>();
    env_kernel<<<(OUT_FULL + 255) / 256, 256>>>();

    // 1) tensor-core (HMMA) GEMM -> g_h
    dim3 g1(N_PAD / 128, M_TOTAL / 128);   // (9, 128)
    gemm_mma_kernel<<<g1, 256, GEMM_SMEM>>>(bias);

    // 2) spectrum -> half-size irfft -> window -> g_frames
    ifft_kernel<<<M_TOTAL, 256>>>();

    // 3) overlap-add * 1/env -> out
    int total = BATCH * OUT_LEN;
    ola_kernel<<<(total + 255) / 256, 256>>>(out);
}

// round 7
// speedup vs baseline: 1.2658x; 1.2658x over previous
#include <cuda_runtime.h>
#include <cuda_bf16.h>
#include <math.h>
#include <stdint.h>

// ---------------------------------------------------------------------------
// Problem constants
// ---------------------------------------------------------------------------
#define BATCH      8
#define T_FRAMES   2048
#define M_TOTAL    (BATCH * T_FRAMES)   // 16384 frames
#define K_DIM      512
#define N_DIM      1026                 // N_FFT + 2
#define N_PAD      1152                 // 9 * 128
#define NBINS      513                  // N_FFT/2 + 1
#define NFFT       1024
#define HOP        256
#define PAD        384                  // (1024-256)/2
#define OUT_FULL   ((T_FRAMES - 1) * HOP + NFFT)  // 525312
#define OUT_LEN    (OUT_FULL - 2 * PAD)           // 524544

// ---------------------------------------------------------------------------
// Scratch (device globals: no runtime allocation allowed)
// ---------------------------------------------------------------------------
__device__ float g_h[(size_t)M_TOTAL * N_DIM];        // linear head output (~67 MB)
__device__ float g_frames[(size_t)M_TOTAL * NFFT];    // windowed iFFT frames (~67 MB)
__device__ __nv_bfloat16 g_xhi[(size_t)M_TOTAL * K_DIM];
__device__ __nv_bfloat16 g_xlo[(size_t)M_TOTAL * K_DIM];
__device__ __nv_bfloat16 g_wthi[(size_t)N_PAD * K_DIM];
__device__ __nv_bfloat16 g_wtlo[(size_t)N_PAD * K_DIM];
// precomputed tables
__device__ float2 g_tw[512];        // e^{+2*pi*i*j/512},  j<512
__device__ float2 g_pretw[512];     // e^{+2*pi*i*k/1024}, k<512  (packing twiddles)
__device__ float  g_win[NFFT];      // hann window
__device__ float  g_env_inv[OUT_FULL];  // 1 / sum win^2

// ---------------------------------------------------------------------------
// baseline-arch PTX helpers (supported on compute_103 WITHOUT 'a')
// ---------------------------------------------------------------------------
__device__ __forceinline__ uint32_t smem_u32(const void* p) {
    return (uint32_t)__cvta_generic_to_shared(p);
}

__device__ __forceinline__ void cp_async16(uint32_t saddr, const void* gptr) {
    asm volatile("cp.async.cg.shared.global [%0], [%1], 16;"
                 :: "r"(saddr), "l"(gptr));
}
#define CP_COMMIT() asm volatile("cp.async.commit_group;" ::: "memory")
#define CP_WAIT0()  asm volatile("cp.async.wait_group 0;" ::: "memory")

#define LDSM_X4(r0, r1, r2, r3, addr) \
    asm volatile("ldmatrix.sync.aligned.m8n8.x4.shared.b16 {%0,%1,%2,%3}, [%4];" \
                 : "=r"(r0), "=r"(r1), "=r"(r2), "=r"(r3) : "r"(addr))

#define MMA16816(c, a0, a1, a2, a3, b0, b1) \
    asm volatile("mma.sync.aligned.m16n8k16.row.col.f32.bf16.bf16.f32 " \
                 "{%0,%1,%2,%3}, {%4,%5,%6,%7}, {%8,%9}, {%0,%1,%2,%3};" \
                 : "+f"((c)[0]), "+f"((c)[1]), "+f"((c)[2]), "+f"((c)[3]) \
                 : "r"(a0), "r"(a1), "r"(a2), "r"(a3), "r"(b0), "r"(b1))

// ---------------------------------------------------------------------------
// complex helpers
// ---------------------------------------------------------------------------
__device__ __forceinline__ float2 cadd(float2 a, float2 b) { return make_float2(a.x + b.x, a.y + b.y); }
__device__ __forceinline__ float2 csub(float2 a, float2 b) { return make_float2(a.x - b.x, a.y - b.y); }
__device__ __forceinline__ float2 cmul(float2 a, float2 b) {
    return make_float2(a.x * b.x - a.y * b.y, a.x * b.y + a.y * b.x);
}
__device__ __forceinline__ float2 cmuli(float2 a) { return make_float2(-a.y, a.x); }  // * i

// inverse 8-point DFT: X[m] = sum_k c[k] e^{+2*pi*i*k*m/8}
__device__ __forceinline__ void ifft8(const float2 c[8], float2 X[8]) {
    const float r = 0.70710678118654752f;
    // FFT4 over even samples (c0,c2,c4,c6)
    float2 t0 = cadd(c[0], c[4]), t1 = csub(c[0], c[4]);
    float2 t2 = cadd(c[2], c[6]), t3 = cmuli(csub(c[2], c[6]));
    float2 E0 = cadd(t0, t2), E1 = cadd(t1, t3), E2 = csub(t0, t2), E3 = csub(t1, t3);
    // FFT4 over odd samples (c1,c3,c5,c7)
    float2 u0 = cadd(c[1], c[5]), u1 = csub(c[1], c[5]);
    float2 u2 = cadd(c[3], c[7]), u3 = cmuli(csub(c[3], c[7]));
    float2 O0 = cadd(u0, u2), O1 = cadd(u1, u3), O2 = csub(u0, u2), O3 = csub(u1, u3);
    // twiddle odd outputs by W8^m (inverse sign): 1, (r+ri), i, (-r+ri)
    float2 W1 = make_float2(r * (O1.x - O1.y), r * (O1.x + O1.y));
    float2 W2 = cmuli(O2);
    float2 W3 = make_float2(-r * (O3.x + O3.y), r * (O3.x - O3.y));
    X[0] = cadd(E0, O0); X[4] = csub(E0, O0);
    X[1] = cadd(E1, W1); X[5] = csub(E1, W1);
    X[2] = cadd(E2, W2); X[6] = csub(E2, W2);
    X[3] = cadd(E3, W3); X[7] = csub(E3, W3);
}

// ---------------------------------------------------------------------------
// Prep: split x (fp32) into bf16 hi/lo
// ---------------------------------------------------------------------------
__global__ void __launch_bounds__(256)
split_x_kernel(const float* __restrict__ x)
{
    size_t i = ((size_t)blockIdx.x * 256 + threadIdx.x) * 8;
    float4 a = *(const float4*)(x + i);
    float4 b = *(const float4*)(x + i + 4);
    float v[8] = {a.x, a.y, a.z, a.w, b.x, b.y, b.z, b.w};
    union { __nv_bfloat16 h[8]; uint4 u; } H, L;
#pragma unroll
    for (int j = 0; j < 8; j++) {
        __nv_bfloat16 hi = __float2bfloat16(v[j]);
        H.h[j] = hi;
        L.h[j] = __float2bfloat16(v[j] - __bfloat162float(hi));
    }
    *(uint4*)&g_xhi[i] = H.u;
    *(uint4*)&g_xlo[i] = L.u;
}

// ---------------------------------------------------------------------------
// Prep: W [K, 1026] -> Wt hi/lo [1152, 512] bf16 (transposed, padded)
// ---------------------------------------------------------------------------
__global__ void __launch_bounds__(256)
prep_w_kernel(const float* __restrict__ W)
{
    int idx = blockIdx.x * 256 + threadIdx.x;
    if (idx >= N_PAD * K_DIM) return;
    int n = idx >> 9;
    int k = idx & 511;
    float v = (n < N_DIM) ? W[(size_t)k * N_DIM + n] : 0.0f;
    __nv_bfloat16 hi = __float2bfloat16(v);
    g_wthi[idx] = hi;
    g_wtlo[idx] = __float2bfloat16(v - __bfloat162float(hi));
}

// ---------------------------------------------------------------------------
// Prep: trig tables (twiddles, packing twiddles, hann window)
// ---------------------------------------------------------------------------
__global__ void __launch_bounds__(256)
tables_kernel()
{
    int i = blockIdx.x * 256 + threadIdx.x;     // 0..1023
    float s, c;
    if (i < 512) {                               // e^{2*pi*i*j/512}
        sincospif((float)i * (1.0f / 256.0f), &s, &c);
        g_tw[i] = make_float2(c, s);
    }
    if (i < 512) {                               // e^{2*pi*i*k/1024}
        sincospif((float)i * (1.0f / 512.0f), &s, &c);
        g_pretw[i] = make_float2(c, s);
    }
    if (i < NFFT) {
        g_win[i] = 0.5f * (1.0f - cospif((float)i * (1.0f / 512.0f)));
    }
}

// ---------------------------------------------------------------------------
// Prep: envelope reciprocal (batch-independent)
// ---------------------------------------------------------------------------
__global__ void __launch_bounds__(256)
env_kernel()
{
    int m = blockIdx.x * 256 + threadIdx.x;
    if (m >= OUT_FULL) return;
    int t_hi = m >> 8;
    if (t_hi > T_FRAMES - 1) t_hi = T_FRAMES - 1;
    int t_lo = (m >= (NFFT - HOP)) ? ((m - (NFFT - HOP)) >> 8) : 0;
    float env = 0.0f;
    for (int t = t_lo; t <= t_hi; t++) {
        int n = m - (t << 8);
        float win = 0.5f * (1.0f - cospif((float)n * (1.0f / 512.0f)));
        env += win * win;
    }
    g_env_inv[m] = (env > 0.0f) ? (1.0f / env) : 0.0f;
}

// ---------------------------------------------------------------------------
// Kernel 1: HMMA GEMM  h = x @ W + b  via 3x-bf16 split on mma.sync.m16n8k16.
// ---------------------------------------------------------------------------
#define MAT_BYTES   16384
#define STAGE_BYTES 65536
#define GEMM_SMEM   (2 * STAGE_BYTES)     // 128 KB

__device__ __forceinline__ void load_stage(uint32_t sdst,
                                           const __nv_bfloat16* const* srcs,
                                           int k0, int tid)
{
#pragma unroll
    for (int m = 0; m < 4; m++) {
        const __nv_bfloat16* __restrict__ src = srcs[m] + k0;
#pragma unroll
        for (int t = 0; t < 4; t++) {
            int idx = tid + (t << 8);
            int row = idx >> 3;
            int g   = idx & 7;
            uint32_t saddr = sdst + (m << 14) + (row << 7) + ((g ^ (row & 7)) << 4);
            cp_async16(saddr, src + (size_t)row * K_DIM + (g << 3));
        }
    }
}

__global__ void __launch_bounds__(256)
gemm_mma_kernel(const float* __restrict__ bias)
{
    extern __shared__ __align__(128) char smem[];
    const int tid  = threadIdx.x;
    const int lane = tid & 31;
    const int warp = tid >> 5;
    const int wm   = (warp >> 2) << 6;
    const int wn   = (warp & 3) << 5;
    const int bm   = blockIdx.y << 7;
    const int bn   = blockIdx.x << 7;
    const uint32_t sbase = smem_u32(smem);

    const __nv_bfloat16* srcs[4] = {
        g_xhi  + (size_t)bm * K_DIM,
        g_xlo  + (size_t)bm * K_DIM,
        g_wthi + (size_t)bn * K_DIM,
        g_wtlo + (size_t)bn * K_DIM
    };

    float acc[4][4][4];
#pragma unroll
    for (int i = 0; i < 4; i++)
#pragma unroll
        for (int j = 0; j < 4; j++)
#pragma unroll
            for (int r = 0; r < 4; r++) acc[i][j][r] = 0.0f;

    const int a_row  = wm + (lane & 15);
    const int a_gadd = (lane >> 4);
    const int b_row  = wn + (lane & 7) + ((lane >> 4) << 3);
    const int b_gadd = ((lane >> 3) & 1);

    load_stage(sbase, srcs, 0, tid);
    CP_COMMIT();

    for (int ck = 0; ck < K_DIM / 64; ck++) {
        CP_WAIT0();
        __syncthreads();
        if (ck + 1 < K_DIM / 64)
            load_stage(sbase + (((ck + 1) & 1) ? STAGE_BYTES : 0), srcs,
                       (ck + 1) << 6, tid);
        CP_COMMIT();

        const uint32_t stg = sbase + ((ck & 1) ? STAGE_BYTES : 0);

#pragma unroll
        for (int s16 = 0; s16 < 4; s16++) {
            const int g0 = (s16 << 1);
            uint32_t a[4][4], bh[2][4], bl[2][4];

#pragma unroll
            for (int i = 0; i < 4; i++) {
                int row = a_row + (i << 4);
                int g   = g0 + a_gadd;
                uint32_t addr = stg + (row << 7) + ((g ^ (row & 7)) << 4);
                LDSM_X4(a[i][0], a[i][1], a[i][2], a[i][3], addr);
            }
#pragma unroll
            for (int j2 = 0; j2 < 2; j2++) {
                int row = b_row + (j2 << 4);
                int g   = g0 + b_gadd;
                uint32_t boff = (row << 7) + ((g ^ (row & 7)) << 4);
                LDSM_X4(bh[j2][0], bh[j2][1], bh[j2][2], bh[j2][3],
                        stg + 2 * MAT_BYTES + boff);
                LDSM_X4(bl[j2][0], bl[j2][1], bl[j2][2], bl[j2][3],
                        stg + 3 * MAT_BYTES + boff);
            }
#pragma unroll
            for (int i = 0; i < 4; i++)
#pragma unroll
                for (int j = 0; j < 4; j++)
                    MMA16816(acc[i][j], a[i][0], a[i][1], a[i][2], a[i][3],
                             bh[j >> 1][(j & 1) << 1], bh[j >> 1][((j & 1) << 1) + 1]);
#pragma unroll
            for (int i = 0; i < 4; i++)
#pragma unroll
                for (int j = 0; j < 4; j++)
                    MMA16816(acc[i][j], a[i][0], a[i][1], a[i][2], a[i][3],
                             bl[j >> 1][(j & 1) << 1], bl[j >> 1][((j & 1) << 1) + 1]);
#pragma unroll
            for (int i = 0; i < 4; i++) {
                int row = a_row + (i << 4);
                int g   = g0 + a_gadd;
                uint32_t addr = stg + MAT_BYTES + (row << 7) + ((g ^ (row & 7)) << 4);
                LDSM_X4(a[i][0], a[i][1], a[i][2], a[i][3], addr);
            }
#pragma unroll
            for (int i = 0; i < 4; i++)
#pragma unroll
                for (int j = 0; j < 4; j++)
                    MMA16816(acc[i][j], a[i][0], a[i][1], a[i][2], a[i][3],
                             bh[j >> 1][(j & 1) << 1], bh[j >> 1][((j & 1) << 1) + 1]);
        }
    }

    const int r0 = bm + wm + (lane >> 2);
    const int c0 = bn + wn + ((lane & 3) << 1);
#pragma unroll
    for (int j = 0; j < 4; j++) {
        int col = c0 + (j << 3);
        if (col < N_DIM) {
            float bx = bias[col];
            float by = bias[col + 1];
#pragma unroll
            for (int i = 0; i < 4; i++) {
                int row = r0 + (i << 4);
                *(float2*)&g_h[(size_t)row * N_DIM + col] =
                    make_float2(acc[i][j][0] + bx, acc[i][j][1] + by);
                *(float2*)&g_h[(size_t)(row + 8) * N_DIM + col] =
                    make_float2(acc[i][j][2] + bx, acc[i][j][3] + by);
            }
        }
    }
}

// ---------------------------------------------------------------------------
// Kernel 2: spectrum -> 512-pt inverse FFT as 3x radix-8 register passes
// (2 smem transposes, 64 threads/frame, 4 frames/block) -> window -> frames.
//
// Hermitian packing (same as passing R5 version, incl. DC/Nyquist Im=0):
//   E=(X[k]+conj(X[512-k]))/2, D=(X[k]-conj(X[512-k]))/2,
//   Z[k]=E + i*(pretw[k]*D);  z = IFFT512(Z);  x[2n]=Re z[n], x[2n+1]=Im z[n]
//
// IFFT512 decomposition (k = 64*k1 + 8*j1 + j2,  n = n1 + 8*m1 + 64*m2):
//   A(n1,k2)   = IFFT8_{k1} Z[64*k1+k2],           then * tw512[k2*n1]
//   B(n1,m1,j2)= IFFT8_{j1} A(n1,8*j1+j2),         then * tw512[8*j2*m1]
//   z[n]       = IFFT8_{j2} B(n1,m1,j2)  (output index m2)
// smem layouts (strides 68/66 keep every access <=2-way bank conflicted):
//   L (n1,k2)    = (k2>>3)*68 + n1*8 + (k2&7)
//   L2(n1,m1,j2) = j2*66 + n1*8 + m1
// ---------------------------------------------------------------------------
__global__ void __launch_bounds__(256)
ifft_kernel()
{
    __shared__ float2 s_spec[4][513];   // packed spectrum per frame
    __shared__ float2 s_buf[4][540];    // transpose buffer per frame
    __shared__ float2 s_tw[512];        // e^{2*pi*i*j/512}

    const int tid = threadIdx.x;
    const int fid = tid >> 6;                      // frame within block
    const int t   = tid & 63;                      // thread within frame
    const int f   = (blockIdx.x << 2) + fid;       // global frame id
    const float* __restrict__ h = g_h + (size_t)f * N_DIM;

    // twiddle table to smem
    s_tw[tid]       = g_tw[tid];
    s_tw[tid + 256] = g_tw[tid + 256];

    // spectrum: S_k = min(exp(h_k),100) * (cos p_k + i sin p_k)
    for (int k = t; k <= 512; k += 64) {
        float mag = fminf(expf(h[k]), 100.0f);
        float s, c;
        sincosf(h[NBINS + k], &s, &c);
        if (k == 0 || k == 512) s = 0.0f;          // irfft ignores Im of DC/Nyquist
        s_spec[fid][k] = make_float2(mag * c, mag * s);
    }
    __syncthreads();

    // ---- pass A: pack + IFFT8 over k1 (k2 = t) ----
    {
        float2 c[8];
#pragma unroll
        for (int k1 = 0; k1 < 8; k1++) {
            int k = (k1 << 6) + t;
            float2 Xk = s_spec[fid][k];
            float2 Xr = s_spec[fid][512 - k];
            float Ex = 0.5f * (Xk.x + Xr.x);
            float Ey = 0.5f * (Xk.y - Xr.y);
            float Dx = 0.5f * (Xk.x - Xr.x);
            float Dy = 0.5f * (Xk.y + Xr.y);
            float2 w = g_pretw[k];
            // Z = E + i*(w*D)
            c[k1] = make_float2(Ex - (w.x * Dy + w.y * Dx),
                                Ey + (w.x * Dx - w.y * Dy));
        }
        float2 X[8];
        ifft8(c, X);
#pragma unroll
        for (int n1 = 1; n1 < 8; n1++) X[n1] = cmul(X[n1], s_tw[t * n1]);
        const int base = (t >> 3) * 68 + (t & 7);
#pragma unroll
        for (int n1 = 0; n1 < 8; n1++) s_buf[fid][base + (n1 << 3)] = X[n1];
    }
    __syncthreads();

    // ---- pass B: IFFT8 over j1, thread = (n1, j2) ----
    {
        const int n1 = t >> 3, j2 = t & 7;
        float2 y[8];
#pragma unroll
        for (int j1 = 0; j1 < 8; j1++) y[j1] = s_buf[fid][j1 * 68 + (n1 << 3) + j2];
        __syncthreads();                          // reads done before in-place writes
        float2 V[8];
        ifft8(y, V);
#pragma unroll
        for (int m1 = 1; m1 < 8; m1++) V[m1] = cmul(V[m1], s_tw[((j2 * m1) << 3)]);
        const int base = j2 * 66 + (n1 << 3);
#pragma unroll
        for (int m1 = 0; m1 < 8; m1++) s_buf[fid][base + m1] = V[m1];
    }
    __syncthreads();

    // ---- pass C: IFFT8 over j2, thread = (n1, m1); scale + window + store ----
    {
        const int n1 = t >> 3, m1 = t & 7;
        float2 d[8];
#pragma unroll
        for (int j2 = 0; j2 < 8; j2++) d[j2] = s_buf[fid][j2 * 66 + (n1 << 3) + m1];
        float2 X[8];
        ifft8(d, X);
        const float inv = 1.0f / 512.0f;
        float* __restrict__ fr = g_frames + (size_t)f * NFFT;
        const int nb = n1 + (m1 << 3);
#pragma unroll
        for (int m2 = 0; m2 < 8; m2++) {
            int n = nb + (m2 << 6);
            float2 w2 = *(const float2*)&g_win[2 * n];
            *(float2*)&fr[2 * n] = make_float2(X[m2].x * inv * w2.x,
                                               X[m2].y * inv * w2.y);
        }
    }
}

// ---------------------------------------------------------------------------
// Kernel 3: overlap-add (gather) * precomputed 1/env — no transcendentals
// ---------------------------------------------------------------------------
__global__ void __launch_bounds__(256)
ola_kernel(float* __restrict__ out)
{
    int i = blockIdx.x * blockDim.x + threadIdx.x;
    if (i >= BATCH * OUT_LEN) return;
    int b  = i / OUT_LEN;
    int mo = i - b * OUT_LEN;
    int m  = mo + PAD;

    int t_hi = m >> 8;
    if (t_hi > T_FRAMES - 1) t_hi = T_FRAMES - 1;
    int t_lo = (m >= (NFFT - HOP)) ? ((m - (NFFT - HOP)) >> 8) : 0;

    float acc = 0.0f;
    const float* __restrict__ base = g_frames + (size_t)b * T_FRAMES * NFFT;
#pragma unroll 4
    for (int t = t_lo; t <= t_hi; t++) {
        acc += base[(size_t)t * NFFT + (m - (t << 8))];
    }
    out[i] = acc * g_env_inv[m];
}

// ---------------------------------------------------------------------------
// Launch
// ---------------------------------------------------------------------------
extern "C" void kernel_launch(void* const* d_in, const int* in_sizes, int n_in,
                              void* d_out, int out_size)
{
    const float* x    = (const float*)d_in[0];   // [8, 2048, 512]
    const float* W    = (const float*)d_in[1];   // [512, 1026]
    const float* bias = (const float*)d_in[2];   // [1026]
    float* out = (float*)d_out;                  // [8, 524544]

    cudaFuncSetAttribute(gemm_mma_kernel,
                         cudaFuncAttributeMaxDynamicSharedMemorySize,
                         GEMM_SMEM);

    // 0) prep: bf16 splits + tables + envelope
    split_x_kernel<<<(M_TOTAL * K_DIM) / (256 * 8), 256>>>(x);
    prep_w_kernel<<<(N_PAD * K_DIM + 255) / 256, 256>>>(W);
    tables_kernel<<<4, 256>>>();
    env_kernel<<<(OUT_FULL + 255) / 256, 256>>>();

    // 1) tensor-core (HMMA) GEMM -> g_h
    dim3 g1(N_PAD / 128, M_TOTAL / 128);   // (9, 128)
    gemm_mma_kernel<<<g1, 256, GEMM_SMEM>>>(bias);

    // 2) spectrum -> radix-8 register irfft -> window -> g_frames
    ifft_kernel<<<M_TOTAL / 4, 256>>>();

    // 3) overlap-add * 1/env -> out
    int total = BATCH * OUT_LEN;
    ola_kernel<<<(total + 255) / 256, 256>>>(out);
}

// round 8
// speedup vs baseline: 1.3323x; 1.0526x over previous
#include <cuda_runtime.h>
#include <cuda_bf16.h>
#include <math.h>
#include <stdint.h>

// ---------------------------------------------------------------------------
// Problem constants
// ---------------------------------------------------------------------------
#define BATCH      8
#define T_FRAMES   2048
#define M_TOTAL    (BATCH * T_FRAMES)   // 16384 frames
#define K_DIM      512
#define N_DIM      1026                 // N_FFT + 2
#define N_PAD      1152                 // 9 * 128
#define NBINS      513                  // N_FFT/2 + 1
#define NFFT       1024
#define HOP        256
#define PAD        384                  // (1024-256)/2
#define OUT_FULL   ((T_FRAMES - 1) * HOP + NFFT)  // 525312
#define OUT_LEN    (OUT_FULL - 2 * PAD)           // 524544

// ---------------------------------------------------------------------------
// Scratch (device globals: no runtime allocation allowed)
// ---------------------------------------------------------------------------
__device__ float g_h[(size_t)M_TOTAL * N_DIM];        // linear head output (~67 MB)
__device__ float g_frames[(size_t)M_TOTAL * NFFT];    // windowed iFFT frames (~67 MB)
__device__ __nv_bfloat16 g_xhi[(size_t)M_TOTAL * K_DIM];
__device__ __nv_bfloat16 g_xlo[(size_t)M_TOTAL * K_DIM];
__device__ __nv_bfloat16 g_wthi[(size_t)N_PAD * K_DIM];
__device__ __nv_bfloat16 g_wtlo[(size_t)N_PAD * K_DIM];
// precomputed tables
__device__ float2 g_tw[512];        // e^{+2*pi*i*j/512},  j<512
__device__ float2 g_pretw[512];     // e^{+2*pi*i*k/1024}, k<512  (packing twiddles)
__device__ float  g_win[NFFT];      // hann window
__device__ float  g_env_inv[OUT_FULL];  // 1 / sum win^2

// ---------------------------------------------------------------------------
// baseline-arch PTX helpers (supported on compute_103 WITHOUT 'a')
// ---------------------------------------------------------------------------
__device__ __forceinline__ uint32_t smem_u32(const void* p) {
    return (uint32_t)__cvta_generic_to_shared(p);
}

__device__ __forceinline__ void cp_async16(uint32_t saddr, const void* gptr) {
    asm volatile("cp.async.cg.shared.global [%0], [%1], 16;"
                 :: "r"(saddr), "l"(gptr));
}
#define CP_COMMIT() asm volatile("cp.async.commit_group;" ::: "memory")
#define CP_WAIT0()  asm volatile("cp.async.wait_group 0;" ::: "memory")

#define LDSM_X4(r0, r1, r2, r3, addr) \
    asm volatile("ldmatrix.sync.aligned.m8n8.x4.shared.b16 {%0,%1,%2,%3}, [%4];" \
                 : "=r"(r0), "=r"(r1), "=r"(r2), "=r"(r3) : "r"(addr))

#define MMA16816(c, a0, a1, a2, a3, b0, b1) \
    asm volatile("mma.sync.aligned.m16n8k16.row.col.f32.bf16.bf16.f32 " \
                 "{%0,%1,%2,%3}, {%4,%5,%6,%7}, {%8,%9}, {%0,%1,%2,%3};" \
                 : "+f"((c)[0]), "+f"((c)[1]), "+f"((c)[2]), "+f"((c)[3]) \
                 : "r"(a0), "r"(a1), "r"(a2), "r"(a3), "r"(b0), "r"(b1))

// ---------------------------------------------------------------------------
// complex helpers
// ---------------------------------------------------------------------------
__device__ __forceinline__ float2 cadd(float2 a, float2 b) { return make_float2(a.x + b.x, a.y + b.y); }
__device__ __forceinline__ float2 csub(float2 a, float2 b) { return make_float2(a.x - b.x, a.y - b.y); }
__device__ __forceinline__ float2 cmul(float2 a, float2 b) {
    return make_float2(a.x * b.x - a.y * b.y, a.x * b.y + a.y * b.x);
}
__device__ __forceinline__ float2 cmuli(float2 a) { return make_float2(-a.y, a.x); }  // * i

// inverse 8-point DFT: X[m] = sum_k c[k] e^{+2*pi*i*k*m/8}
__device__ __forceinline__ void ifft8(const float2 c[8], float2 X[8]) {
    const float r = 0.70710678118654752f;
    float2 t0 = cadd(c[0], c[4]), t1 = csub(c[0], c[4]);
    float2 t2 = cadd(c[2], c[6]), t3 = cmuli(csub(c[2], c[6]));
    float2 E0 = cadd(t0, t2), E1 = cadd(t1, t3), E2 = csub(t0, t2), E3 = csub(t1, t3);
    float2 u0 = cadd(c[1], c[5]), u1 = csub(c[1], c[5]);
    float2 u2 = cadd(c[3], c[7]), u3 = cmuli(csub(c[3], c[7]));
    float2 O0 = cadd(u0, u2), O1 = cadd(u1, u3), O2 = csub(u0, u2), O3 = csub(u1, u3);
    float2 W1 = make_float2(r * (O1.x - O1.y), r * (O1.x + O1.y));
    float2 W2 = cmuli(O2);
    float2 W3 = make_float2(-r * (O3.x + O3.y), r * (O3.x - O3.y));
    X[0] = cadd(E0, O0); X[4] = csub(E0, O0);
    X[1] = cadd(E1, W1); X[5] = csub(E1, W1);
    X[2] = cadd(E2, W2); X[6] = csub(E2, W2);
    X[3] = cadd(E3, W3); X[7] = csub(E3, W3);
}

// ---------------------------------------------------------------------------
// Prep: split x (fp32) into bf16 hi/lo
// ---------------------------------------------------------------------------
__global__ void __launch_bounds__(256)
split_x_kernel(const float* __restrict__ x)
{
    size_t i = ((size_t)blockIdx.x * 256 + threadIdx.x) * 8;
    float4 a = *(const float4*)(x + i);
    float4 b = *(const float4*)(x + i + 4);
    float v[8] = {a.x, a.y, a.z, a.w, b.x, b.y, b.z, b.w};
    union { __nv_bfloat16 h[8]; uint4 u; } H, L;
#pragma unroll
    for (int j = 0; j < 8; j++) {
        __nv_bfloat16 hi = __float2bfloat16(v[j]);
        H.h[j] = hi;
        L.h[j] = __float2bfloat16(v[j] - __bfloat162float(hi));
    }
    *(uint4*)&g_xhi[i] = H.u;
    *(uint4*)&g_xlo[i] = L.u;
}

// ---------------------------------------------------------------------------
// Prep: W [K, 1026] -> Wt hi/lo [1152, 512] bf16 (transposed, padded)
// ---------------------------------------------------------------------------
__global__ void __launch_bounds__(256)
prep_w_kernel(const float* __restrict__ W)
{
    int idx = blockIdx.x * 256 + threadIdx.x;
    if (idx >= N_PAD * K_DIM) return;
    int n = idx >> 9;
    int k = idx & 511;
    float v = (n < N_DIM) ? W[(size_t)k * N_DIM + n] : 0.0f;
    __nv_bfloat16 hi = __float2bfloat16(v);
    g_wthi[idx] = hi;
    g_wtlo[idx] = __float2bfloat16(v - __bfloat162float(hi));
}

// ---------------------------------------------------------------------------
// Prep: trig tables
// ---------------------------------------------------------------------------
__global__ void __launch_bounds__(256)
tables_kernel()
{
    int i = blockIdx.x * 256 + threadIdx.x;     // 0..1023
    float s, c;
    if (i < 512) {                               // e^{2*pi*i*j/512}
        sincospif((float)i * (1.0f / 256.0f), &s, &c);
        g_tw[i] = make_float2(c, s);
    }
    if (i < 512) {                               // e^{2*pi*i*k/1024}
        sincospif((float)i * (1.0f / 512.0f), &s, &c);
        g_pretw[i] = make_float2(c, s);
    }
    if (i < NFFT) {
        g_win[i] = 0.5f * (1.0f - cospif((float)i * (1.0f / 512.0f)));
    }
}

// ---------------------------------------------------------------------------
// Prep: envelope reciprocal (batch-independent)
// ---------------------------------------------------------------------------
__global__ void __launch_bounds__(256)
env_kernel()
{
    int m = blockIdx.x * 256 + threadIdx.x;
    if (m >= OUT_FULL) return;
    int t_hi = m >> 8;
    if (t_hi > T_FRAMES - 1) t_hi = T_FRAMES - 1;
    int t_lo = (m >= (NFFT - HOP)) ? ((m - (NFFT - HOP)) >> 8) : 0;
    float env = 0.0f;
    for (int t = t_lo; t <= t_hi; t++) {
        int n = m - (t << 8);
        float win = 0.5f * (1.0f - cospif((float)n * (1.0f / 512.0f)));
        env += win * win;
    }
    g_env_inv[m] = (env > 0.0f) ? (1.0f / env) : 0.0f;
}

// ---------------------------------------------------------------------------
// Kernel 1: HMMA GEMM  h = x @ W + b  via 3x-bf16 split on mma.sync.m16n8k16.
// CTA tile 256(M) x 128(N), BK=64, 8 warps (warp tile 64x64), 2-stage cp.async.
// ---------------------------------------------------------------------------
#define A_MAT_BYTES 32768                 // 256 x 64 bf16
#define B_MAT_BYTES 16384                 // 128 x 64 bf16
#define STAGE_BYTES (2 * A_MAT_BYTES + 2 * B_MAT_BYTES)   // 98304
#define GEMM_SMEM   (2 * STAGE_BYTES)     // 196608
// offsets within a stage
#define OFF_AH 0
#define OFF_AL A_MAT_BYTES
#define OFF_BH (2 * A_MAT_BYTES)
#define OFF_BL (2 * A_MAT_BYTES + B_MAT_BYTES)

__device__ __forceinline__ void load_stage(uint32_t sdst,
                                           const __nv_bfloat16* pAh,
                                           const __nv_bfloat16* pAl,
                                           const __nv_bfloat16* pBh,
                                           const __nv_bfloat16* pBl,
                                           int k0, int tid)
{
    // A matrices: 256 rows x 8 granules = 2048 cp per matrix (8 iters)
#pragma unroll
    for (int t = 0; t < 8; t++) {
        int idx = tid + (t << 8);
        int row = idx >> 3;
        int g   = idx & 7;
        uint32_t soff = (row << 7) + ((g ^ (row & 7)) << 4);
        size_t goff = (size_t)row * K_DIM + k0 + (g << 3);
        cp_async16(sdst + OFF_AH + soff, pAh + goff);
        cp_async16(sdst + OFF_AL + soff, pAl + goff);
    }
    // B matrices: 128 rows x 8 granules = 1024 cp per matrix (4 iters)
#pragma unroll
    for (int t = 0; t < 4; t++) {
        int idx = tid + (t << 8);
        int row = idx >> 3;
        int g   = idx & 7;
        uint32_t soff = (row << 7) + ((g ^ (row & 7)) << 4);
        size_t goff = (size_t)row * K_DIM + k0 + (g << 3);
        cp_async16(sdst + OFF_BH + soff, pBh + goff);
        cp_async16(sdst + OFF_BL + soff, pBl + goff);
    }
}

__global__ void __launch_bounds__(256, 1)
gemm_mma_kernel(const float* __restrict__ bias)
{
    extern __shared__ __align__(128) char smem[];
    const int tid  = threadIdx.x;
    const int lane = tid & 31;
    const int warp = tid >> 5;
    const int wm   = (warp >> 1) << 6;   // 0,64,128,192
    const int wn   = (warp & 1) << 6;    // 0,64
    const int bm   = blockIdx.y << 8;    // 256-row tiles
    const int bn   = blockIdx.x << 7;    // 128-col tiles
    const uint32_t sbase = smem_u32(smem);

    const __nv_bfloat16* pAh = g_xhi  + (size_t)bm * K_DIM;
    const __nv_bfloat16* pAl = g_xlo  + (size_t)bm * K_DIM;
    const __nv_bfloat16* pBh = g_wthi + (size_t)bn * K_DIM;
    const __nv_bfloat16* pBl = g_wtlo + (size_t)bn * K_DIM;

    float acc[4][8][4];
#pragma unroll
    for (int i = 0; i < 4; i++)
#pragma unroll
        for (int j = 0; j < 8; j++)
#pragma unroll
            for (int r = 0; r < 4; r++) acc[i][j][r] = 0.0f;

    const int a_row  = wm + (lane & 15);
    const int a_gadd = (lane >> 4);
    const int b_row  = wn + (lane & 7) + ((lane >> 4) << 3);
    const int b_gadd = ((lane >> 3) & 1);

    load_stage(sbase, pAh, pAl, pBh, pBl, 0, tid);
    CP_COMMIT();

    for (int ck = 0; ck < K_DIM / 64; ck++) {
        CP_WAIT0();
        __syncthreads();
        if (ck + 1 < K_DIM / 64)
            load_stage(sbase + (((ck + 1) & 1) ? STAGE_BYTES : 0),
                       pAh, pAl, pBh, pBl, (ck + 1) << 6, tid);
        CP_COMMIT();

        const uint32_t stg = sbase + ((ck & 1) ? STAGE_BYTES : 0);

#pragma unroll
        for (int s16 = 0; s16 < 4; s16++) {
            const int g0 = (s16 << 1);
            uint32_t a[4][4], bh[4][4], bl[4][4];

            // B(hi), B(lo): 4+4 ldmatrix.x4 covering 64 cols
#pragma unroll
            for (int j2 = 0; j2 < 4; j2++) {
                int row = b_row + (j2 << 4);
                int g   = g0 + b_gadd;
                uint32_t boff = (row << 7) + ((g ^ (row & 7)) << 4);
                LDSM_X4(bh[j2][0], bh[j2][1], bh[j2][2], bh[j2][3],
                        stg + OFF_BH + boff);
                LDSM_X4(bl[j2][0], bl[j2][1], bl[j2][2], bl[j2][3],
                        stg + OFF_BL + boff);
            }
            // A(hi)
#pragma unroll
            for (int i = 0; i < 4; i++) {
                int row = a_row + (i << 4);
                int g   = g0 + a_gadd;
                uint32_t addr = stg + OFF_AH + (row << 7) + ((g ^ (row & 7)) << 4);
                LDSM_X4(a[i][0], a[i][1], a[i][2], a[i][3], addr);
            }
            // pass 1: Ah x Bh
#pragma unroll
            for (int i = 0; i < 4; i++)
#pragma unroll
                for (int j = 0; j < 8; j++)
                    MMA16816(acc[i][j], a[i][0], a[i][1], a[i][2], a[i][3],
                             bh[j >> 1][(j & 1) << 1], bh[j >> 1][((j & 1) << 1) + 1]);
            // pass 2: Ah x Bl
#pragma unroll
            for (int i = 0; i < 4; i++)
#pragma unroll
                for (int j = 0; j < 8; j++)
                    MMA16816(acc[i][j], a[i][0], a[i][1], a[i][2], a[i][3],
                             bl[j >> 1][(j & 1) << 1], bl[j >> 1][((j & 1) << 1) + 1]);
            // A(lo) (reuse regs)
#pragma unroll
            for (int i = 0; i < 4; i++) {
                int row = a_row + (i << 4);
                int g   = g0 + a_gadd;
                uint32_t addr = stg + OFF_AL + (row << 7) + ((g ^ (row & 7)) << 4);
                LDSM_X4(a[i][0], a[i][1], a[i][2], a[i][3], addr);
            }
            // pass 3: Al x Bh
#pragma unroll
            for (int i = 0; i < 4; i++)
#pragma unroll
                for (int j = 0; j < 8; j++)
                    MMA16816(acc[i][j], a[i][0], a[i][1], a[i][2], a[i][3],
                             bh[j >> 1][(j & 1) << 1], bh[j >> 1][((j & 1) << 1) + 1]);
        }
    }

    // epilogue: bias + direct float2 stores
    const int r0 = bm + wm + (lane >> 2);
    const int c0 = bn + wn + ((lane & 3) << 1);
#pragma unroll
    for (int j = 0; j < 8; j++) {
        int col = c0 + (j << 3);
        if (col < N_DIM) {
            float bx = bias[col];
            float by = bias[col + 1];
#pragma unroll
            for (int i = 0; i < 4; i++) {
                int row = r0 + (i << 4);
                *(float2*)&g_h[(size_t)row * N_DIM + col] =
                    make_float2(acc[i][j][0] + bx, acc[i][j][1] + by);
                *(float2*)&g_h[(size_t)(row + 8) * N_DIM + col] =
                    make_float2(acc[i][j][2] + bx, acc[i][j][3] + by);
            }
        }
    }
}

// ---------------------------------------------------------------------------
// Kernel 2: spectrum -> 512-pt inverse FFT as 3x radix-8 register passes
// (2 smem transposes, 64 threads/frame, 4 frames/block) -> window -> frames.
// ---------------------------------------------------------------------------
__global__ void __launch_bounds__(256)
ifft_kernel()
{
    __shared__ float2 s_spec[4][513];   // packed spectrum per frame
    __shared__ float2 s_buf[4][540];    // transpose buffer per frame
    __shared__ float2 s_tw[512];        // e^{2*pi*i*j/512}

    const int tid = threadIdx.x;
    const int fid = tid >> 6;                      // frame within block
    const int t   = tid & 63;                      // thread within frame
    const int f   = (blockIdx.x << 2) + fid;       // global frame id
    const float* __restrict__ h = g_h + (size_t)f * N_DIM;

    s_tw[tid]       = g_tw[tid];
    s_tw[tid + 256] = g_tw[tid + 256];

    // spectrum: S_k = min(exp(h_k),100) * (cos p_k + i sin p_k)
    for (int k = t; k <= 512; k += 64) {
        float mag = fminf(__expf(h[k]), 100.0f);
        float s, c;
        __sincosf(h[NBINS + k], &s, &c);
        if (k == 0 || k == 512) s = 0.0f;          // irfft ignores Im of DC/Nyquist
        s_spec[fid][k] = make_float2(mag * c, mag * s);
    }
    __syncthreads();

    // ---- pass A: pack + IFFT8 over k1 (k2 = t) ----
    {
        float2 c[8];
#pragma unroll
        for (int k1 = 0; k1 < 8; k1++) {
            int k = (k1 << 6) + t;
            float2 Xk = s_spec[fid][k];
            float2 Xr = s_spec[fid][512 - k];
            float Ex = 0.5f * (Xk.x + Xr.x);
            float Ey = 0.5f * (Xk.y - Xr.y);
            float Dx = 0.5f * (Xk.x - Xr.x);
            float Dy = 0.5f * (Xk.y + Xr.y);
            float2 w = g_pretw[k];
            c[k1] = make_float2(Ex - (w.x * Dy + w.y * Dx),
                                Ey + (w.x * Dx - w.y * Dy));
        }
        float2 X[8];
        ifft8(c, X);
#pragma unroll
        for (int n1 = 1; n1 < 8; n1++) X[n1] = cmul(X[n1], s_tw[t * n1]);
        const int base = (t >> 3) * 68 + (t & 7);
#pragma unroll
        for (int n1 = 0; n1 < 8; n1++) s_buf[fid][base + (n1 << 3)] = X[n1];
    }
    __syncthreads();

    // ---- pass B: IFFT8 over j1, thread = (n1, j2) ----
    {
        const int n1 = t >> 3, j2 = t & 7;
        float2 y[8];
#pragma unroll
        for (int j1 = 0; j1 < 8; j1++) y[j1] = s_buf[fid][j1 * 68 + (n1 << 3) + j2];
        __syncthreads();                          // reads done before in-place writes
        float2 V[8];
        ifft8(y, V);
#pragma unroll
        for (int m1 = 1; m1 < 8; m1++) V[m1] = cmul(V[m1], s_tw[((j2 * m1) << 3)]);
        const int base = j2 * 66 + (n1 << 3);
#pragma unroll
        for (int m1 = 0; m1 < 8; m1++) s_buf[fid][base + m1] = V[m1];
    }
    __syncthreads();

    // ---- pass C: IFFT8 over j2, thread = (n1, m1); scale + window + store ----
    {
        const int n1 = t >> 3, m1 = t & 7;
        float2 d[8];
#pragma unroll
        for (int j2 = 0; j2 < 8; j2++) d[j2] = s_buf[fid][j2 * 66 + (n1 << 3) + m1];
        float2 X[8];
        ifft8(d, X);
        const float inv = 1.0f / 512.0f;
        float* __restrict__ fr = g_frames + (size_t)f * NFFT;
        const int nb = n1 + (m1 << 3);
#pragma unroll
        for (int m2 = 0; m2 < 8; m2++) {
            int n = nb + (m2 << 6);
            float2 w2 = *(const float2*)&g_win[2 * n];
            *(float2*)&fr[2 * n] = make_float2(X[m2].x * inv * w2.x,
                                               X[m2].y * inv * w2.y);
        }
    }
}

// ---------------------------------------------------------------------------
// Kernel 3: overlap-add, 4 outputs/thread, float4 loads, precomputed 1/env.
// A 4-aligned group of m's always lies in one hop cell (256 | cell), so the
// frame range [t_lo, t_hi] is shared by the group.
// ---------------------------------------------------------------------------
__global__ void __launch_bounds__(256)
ola_kernel(float* __restrict__ out)
{
    int g = blockIdx.x * blockDim.x + threadIdx.x;       // group id
    if (g >= (BATCH * OUT_LEN) / 4) return;
    int b   = g / (OUT_LEN / 4);
    int mo0 = (g - b * (OUT_LEN / 4)) << 2;
    int m0  = mo0 + PAD;

    int t_hi = m0 >> 8;
    if (t_hi > T_FRAMES - 1) t_hi = T_FRAMES - 1;
    int t_lo = (m0 >= (NFFT - HOP)) ? ((m0 - (NFFT - HOP)) >> 8) : 0;

    float4 acc = make_float4(0.0f, 0.0f, 0.0f, 0.0f);
    const float* __restrict__ base = g_frames + (size_t)b * T_FRAMES * NFFT;
#pragma unroll 4
    for (int t = t_lo; t <= t_hi; t++) {
        float4 v = *(const float4*)(base + (size_t)t * NFFT + (m0 - (t << 8)));
        acc.x += v.x; acc.y += v.y; acc.z += v.z; acc.w += v.w;
    }
    float4 e = *(const float4*)&g_env_inv[m0];
    *(float4*)&out[(size_t)b * OUT_LEN + mo0] =
        make_float4(acc.x * e.x, acc.y * e.y, acc.z * e.z, acc.w * e.w);
}

// ---------------------------------------------------------------------------
// Launch
// ---------------------------------------------------------------------------
extern "C" void kernel_launch(void* const* d_in, const int* in_sizes, int n_in,
                              void* d_out, int out_size)
{
    const float* x    = (const float*)d_in[0];   // [8, 2048, 512]
    const float* W    = (const float*)d_in[1];   // [512, 1026]
    const float* bias = (const float*)d_in[2];   // [1026]
    float* out = (float*)d_out;                  // [8, 524544]

    cudaFuncSetAttribute(gemm_mma_kernel,
                         cudaFuncAttributeMaxDynamicSharedMemorySize,
                         GEMM_SMEM);

    // 0) prep: bf16 splits + tables + envelope
    split_x_kernel<<<(M_TOTAL * K_DIM) / (256 * 8), 256>>>(x);
    prep_w_kernel<<<(N_PAD * K_DIM + 255) / 256, 256>>>(W);
    tables_kernel<<<4, 256>>>();
    env_kernel<<<(OUT_FULL + 255) / 256, 256>>>();

    // 1) tensor-core (HMMA) GEMM -> g_h
    dim3 g1(N_PAD / 128, M_TOTAL / 256);   // (9, 64)
    gemm_mma_kernel<<<g1, 256, GEMM_SMEM>>>(bias);

    // 2) spectrum -> radix-8 register irfft -> window -> g_frames
    ifft_kernel<<<M_TOTAL / 4, 256>>>();

    // 3) overlap-add * 1/env -> out (4 outputs per thread)
    int groups = (BATCH * OUT_LEN) / 4;
    ola_kernel<<<(groups + 255) / 256, 256>>>(out);
}